// round 14
// baseline (speedup 1.0000x reference)
#include <cuda_runtime.h>
#include <cuda_fp16.h>
#include <cstdint>

// Problem constants
#define BATCH  8
#define SEQ    1024
#define DIM    1024
#define HEADS  16
#define HDIM   64
#define TOKENS (BATCH * SEQ)          // 8192
#define QKVDIM (3 * DIM)              // 3072
#define SCALE  0.03125f               // 1024^-0.5

// ---------------------------------------------------------------------------
// Scratch (device globals: allocation-guard safe)
// ---------------------------------------------------------------------------
__device__ __half g_xhi[(size_t)TOKENS * DIM];
__device__ __half g_w1hi[(size_t)QKVDIM * DIM];      // w_qkv^T [3072][1024]
__device__ __half g_w2hi[(size_t)DIM * DIM];         // w_out^T [1024][1024]
__device__ __half g_qkvhi[(size_t)TOKENS * QKVDIM];  // qkv [8192][3072]
__device__ __half g_ahi[(size_t)TOKENS * DIM];

// ---------------------------------------------------------------------------
// Helpers
// ---------------------------------------------------------------------------
__device__ __forceinline__ uint32_t smem_u32(const void* p) {
    uint32_t a;
    asm("{ .reg .u64 t; cvta.to.shared.u64 t, %1; cvt.u32.u64 %0, t; }" : "=r"(a) : "l"(p));
    return a;
}

__device__ __forceinline__ void cp_async16(uint32_t dst, const void* src) {
    asm volatile("cp.async.cg.shared.global [%0], [%1], 16;\n" :: "r"(dst), "l"(src));
}
#define CP_COMMIT() asm volatile("cp.async.commit_group;\n" ::: "memory")
#define CP_WAIT2()  asm volatile("cp.async.wait_group 2;\n" ::: "memory")
#define CP_WAIT1()  asm volatile("cp.async.wait_group 1;\n" ::: "memory")
#define CP_WAIT0()  asm volatile("cp.async.wait_group 0;\n" ::: "memory")

__device__ __forceinline__ void ldsm_x4(uint32_t* r, uint32_t addr) {
    asm volatile("ldmatrix.sync.aligned.m8n8.x4.shared.b16 {%0,%1,%2,%3}, [%4];"
                 : "=r"(r[0]), "=r"(r[1]), "=r"(r[2]), "=r"(r[3]) : "r"(addr));
}

__device__ __forceinline__ void ldsm_x4_t(uint32_t* r, uint32_t addr) {
    asm volatile("ldmatrix.sync.aligned.m8n8.x4.trans.shared.b16 {%0,%1,%2,%3}, [%4];"
                 : "=r"(r[0]), "=r"(r[1]), "=r"(r[2]), "=r"(r[3]) : "r"(addr));
}

// fp16 HMMA, fp32 accumulate
__device__ __forceinline__ void mma_f16(float* d, const uint32_t* a, const uint32_t* b) {
    asm volatile("mma.sync.aligned.m16n8k16.row.col.f32.f16.f16.f32 "
                 "{%0,%1,%2,%3}, {%4,%5,%6,%7}, {%8,%9}, {%0,%1,%2,%3};"
                 : "+f"(d[0]), "+f"(d[1]), "+f"(d[2]), "+f"(d[3])
                 : "r"(a[0]), "r"(a[1]), "r"(a[2]), "r"(a[3]), "r"(b[0]), "r"(b[1]));
}

// pack two fp32 into f16x2 (lo -> low half)
__device__ __forceinline__ uint32_t pack_f16(float lo, float hi) {
    uint32_t d;
    asm("cvt.rn.f16x2.f32 %0, %1, %2;" : "=r"(d) : "f"(hi), "f"(lo));
    return d;
}

// ---------------------------------------------------------------------------
// Pure fp16 HMMA GEMM (1-pass): C = A[M,K] @ W[N,K]^T
// OUT==0: write fp32 C (+bias).  OUT==2: fp16.
// Block tile 128(M) x 256(N), warp tile 64x64 (8 warps, 2m x 4n), BK=64,
// 1 CTA/SM, 3-stage cp.async pipeline, XOR-swizzled 128B-row smem.
// Per-warp: 8 ldsm_x4 per k16 for 32 mmas -> 128 B/mma L1 traffic.
// ---------------------------------------------------------------------------
#define GK     1024
#define BK     64
#define NITER  (GK / BK)               // 16
#define A_TILE (128 * 128)             // 16 KB [128 rows][64 f16]
#define B_TILE (256 * 128)             // 32 KB [256 rows][64 f16]
#define STAGEB (A_TILE + B_TILE)       // 48 KB
#define NSTAGE 3
#define GEMM_SMEM (NSTAGE * STAGEB)    // 144 KB

template<int OUT>
__global__ __launch_bounds__(256, 1) void gemm_mma(
    const __half* __restrict__ Ahi,
    const __half* __restrict__ Whi,
    const float* __restrict__ bias, float* __restrict__ C,
    __half* __restrict__ Chi, int N)
{
    extern __shared__ char sm[];
    const uint32_t sbase = smem_u32(sm);
    const int tid  = threadIdx.x;
    const int lane = tid & 31;
    const int warp = tid >> 5;
    const int wm = warp & 1;              // 2 warp rows (64 m each)
    const int wn = warp >> 1;             // 4 warp cols (64 n each)
    const int m0 = blockIdx.y * 128;
    const int n0 = blockIdx.x * 256;

    float acc[4][8][4];
    #pragma unroll
    for (int i = 0; i < 4; i++)
        #pragma unroll
        for (int j = 0; j < 8; j++)
            #pragma unroll
            for (int q = 0; q < 4; q++) acc[i][j][q] = 0.f;

    auto soff = [&](int s, int t) -> uint32_t {
        return sbase + s * STAGEB + t * A_TILE;   // t=0: A, t=1: B (B right after A)
    };

    auto load_stage = [&](int s, int k0) {
        // A tile: 128 rows x 8 chunks = 1024
        {
            const char* gp = (const char*)(Ahi + (size_t)m0 * GK + k0);
            #pragma unroll
            for (int j = 0; j < 4; j++) {
                int id = tid + j * 256;
                int r = id >> 3, c = id & 7;
                uint32_t sw = r * 128 + ((c ^ (r & 7)) << 4);
                cp_async16(soff(s, 0) + sw, gp + (size_t)r * (GK * 2) + c * 16);
            }
        }
        // B tile: 256 rows x 8 chunks = 2048
        {
            const char* gp = (const char*)(Whi + (size_t)n0 * GK + k0);
            #pragma unroll
            for (int j = 0; j < 8; j++) {
                int id = tid + j * 256;
                int r = id >> 3, c = id & 7;
                uint32_t sw = r * 128 + ((c ^ (r & 7)) << 4);
                cp_async16(soff(s, 1) + sw, gp + (size_t)r * (GK * 2) + c * 16);
            }
        }
        CP_COMMIT();
    };

    load_stage(0, 0);
    load_stage(1, BK);

    const int sub = lane >> 3, rin = lane & 7;
    const int a_row_off = (sub & 1) * 8 + rin;
    const int a_chunk   = sub >> 1;
    const int b_row_off = (sub >> 1) * 8 + rin;
    const int b_chunk   = sub & 1;

    for (int it = 0; it < NITER; it++) {
        const int s = it % NSTAGE;
        if (it == NITER - 1) { CP_WAIT0(); } else { CP_WAIT1(); }
        __syncthreads();

        const uint32_t aH = soff(s, 0), wH = soff(s, 1);

        #pragma unroll
        for (int ks = 0; ks < 4; ks++) {          // 4 k16 steps per BK=64
            uint32_t Ah[4][4], Bh[8][2];

            #pragma unroll
            for (int mi = 0; mi < 4; mi++) {
                int row = wm * 64 + mi * 16 + a_row_off;
                int ch = ks * 2 + a_chunk;
                uint32_t off = row * 128 + ((ch ^ (row & 7)) << 4);
                ldsm_x4(Ah[mi], aH + off);
            }
            #pragma unroll
            for (int p = 0; p < 4; p++) {
                int row = wn * 64 + p * 16 + b_row_off;
                int ch = ks * 2 + b_chunk;
                uint32_t off = row * 128 + ((ch ^ (row & 7)) << 4);
                uint32_t t0[4];
                ldsm_x4(t0, wH + off);
                Bh[p*2  ][0] = t0[0]; Bh[p*2  ][1] = t0[1];
                Bh[p*2+1][0] = t0[2]; Bh[p*2+1][1] = t0[3];
            }

            #pragma unroll
            for (int mi = 0; mi < 4; mi++)
                #pragma unroll
                for (int ni = 0; ni < 8; ni++)
                    mma_f16(acc[mi][ni], Ah[mi], Bh[ni]);
        }
        if (it + 2 < NITER) load_stage((it + 2) % NSTAGE, (it + 2) * BK);
    }

    const int g = lane >> 2, c2 = (lane & 3) * 2;
    #pragma unroll
    for (int mi = 0; mi < 4; mi++) {
        int row = m0 + wm * 64 + mi * 16 + g;
        #pragma unroll
        for (int ni = 0; ni < 8; ni++) {
            int col = n0 + wn * 64 + ni * 8 + c2;
            if (OUT == 0) {
                float b0 = 0.f, b1 = 0.f;
                if (bias) { b0 = bias[col]; b1 = bias[col + 1]; }
                float2 v0 = make_float2(acc[mi][ni][0] + b0, acc[mi][ni][1] + b1);
                float2 v1 = make_float2(acc[mi][ni][2] + b0, acc[mi][ni][3] + b1);
                *(float2*)&C[(size_t)row * N + col] = v0;
                *(float2*)&C[(size_t)(row + 8) * N + col] = v1;
            } else {
                *(uint32_t*)&Chi[(size_t)row * N + col] =
                    pack_f16(acc[mi][ni][0], acc[mi][ni][1]);
                *(uint32_t*)&Chi[(size_t)(row + 8) * N + col] =
                    pack_f16(acc[mi][ni][2], acc[mi][ni][3]);
            }
        }
    }
}

// ---------------------------------------------------------------------------
// fp32 -> fp16 cast (elementwise, float4)
// ---------------------------------------------------------------------------
__global__ __launch_bounds__(256) void cast_kernel(
    const float* __restrict__ in, __half* __restrict__ hi, int n4)
{
    int i = blockIdx.x * blockDim.x + threadIdx.x;
    if (i >= n4) return;
    float4 v = ((const float4*)in)[i];
    ((uint2*)hi)[i] = make_uint2(pack_f16(v.x, v.y), pack_f16(v.z, v.w));
}

// ---------------------------------------------------------------------------
// fp32 [K][N] -> transposed fp16 [N][K]
// ---------------------------------------------------------------------------
__global__ __launch_bounds__(256) void castT_kernel(
    const float* __restrict__ w, __half* __restrict__ thi, int K, int N)
{
    __shared__ float t[32][33];
    const int n0 = blockIdx.x * 32, k0 = blockIdx.y * 32;
    const int tx = threadIdx.x & 31, ty = threadIdx.x >> 5;
    #pragma unroll
    for (int j = ty; j < 32; j += 8)
        t[j][tx] = w[(size_t)(k0 + j) * N + n0 + tx];
    __syncthreads();
    #pragma unroll
    for (int j = ty; j < 32; j += 8)
        thi[(size_t)(n0 + j) * K + k0 + tx] = __float2half_rn(t[tx][j]);
}

// ---------------------------------------------------------------------------
// HMMA flash attention, pure fp16 (S = Qh Kh^T; O += Ph Vh).
// KV stage = 128 keys (processed as 2x64 halves): halves barriers/waits.
// smem: Q 16KB + 2 stages x (K 16KB + V 16KB) = 80KB; 2 CTAs/SM.
// ---------------------------------------------------------------------------
#define AT_Q    0
#define AT_ST   16384
#define AT_STB  32768
#define AT_KH   0
#define AT_VH   16384
#define AT_SMEM (AT_ST + 2 * AT_STB)   // 81920

__global__ __launch_bounds__(256, 2) void attn_mma(
    const __half* __restrict__ qh, __half* __restrict__ ohi)
{
    extern __shared__ char sm[];
    const uint32_t sb = smem_u32(sm);
    const int tid  = threadIdx.x;
    const int lane = tid & 31;
    const int warp = tid >> 5;
    const int sub = lane >> 3, rin = lane & 7;
    const int g = lane >> 2, t = lane & 3;

    const int qt = blockIdx.x, head = blockIdx.y, batch = blockIdx.z;
    const size_t tok0 = (size_t)batch * SEQ;
    const size_t qbase = (tok0 + qt * 128) * QKVDIM + head * HDIM;

    #pragma unroll
    for (int j = 0; j < 4; j++) {
        int id = tid + j * 256;
        int r = id >> 3, c = id & 7;
        uint32_t sw = r * 128 + ((c ^ (r & 7)) << 4);
        cp_async16(sb + AT_Q + sw, (const char*)(qh + qbase) + (size_t)r * QKVDIM * 2 + c * 16);
    }
    CP_COMMIT();

    // jt indexes 128-key tiles (0..7)
    auto load_kv = [&](int s, int jt) {
        size_t kb = (tok0 + jt * 128) * QKVDIM + DIM + head * HDIM;
        size_t vb = kb + DIM;
        uint32_t st = sb + AT_ST + s * AT_STB;
        #pragma unroll
        for (int j = 0; j < 4; j++) {
            int id = tid + j * 256;
            int r = id >> 3, c = id & 7;     // r = 0..127
            uint32_t sw = r * 128 + ((c ^ (r & 7)) << 4);
            size_t go = (size_t)r * QKVDIM * 2 + c * 16;
            cp_async16(st + AT_KH + sw, (const char*)(qh + kb) + go);
            cp_async16(st + AT_VH + sw, (const char*)(qh + vb) + go);
        }
        CP_COMMIT();
    };

    load_kv(0, 0);
    load_kv(1, 1);

    CP_WAIT2();
    __syncthreads();
    uint32_t Qh[4][4];
    {
        int row = warp * 16 + (sub & 1) * 8 + rin;
        #pragma unroll
        for (int s4 = 0; s4 < 4; s4++) {
            int ch = 2 * s4 + (sub >> 1);
            uint32_t off = row * 128 + ((ch ^ (row & 7)) << 4);
            ldsm_x4(Qh[s4], sb + AT_Q + off);
        }
    }

    float m0 = -1e30f, m1 = -1e30f, l0 = 0.f, l1 = 0.f;
    float O[8][4];
    #pragma unroll
    for (int b = 0; b < 8; b++)
        #pragma unroll
        for (int q = 0; q < 4; q++) O[b][q] = 0.f;

    for (int jt = 0; jt < SEQ / 128; jt++) {          // 8 tiles of 128 keys
        const int s = jt & 1;
        if (jt == SEQ / 128 - 1) { CP_WAIT0(); } else { CP_WAIT1(); }
        __syncthreads();
        const uint32_t stb = sb + AT_ST + s * AT_STB;

        #pragma unroll
        for (int half = 0; half < 2; half++) {        // two 64-key halves
            const int rbase = half * 64;

            float S[8][4];
            #pragma unroll
            for (int b = 0; b < 8; b++)
                #pragma unroll
                for (int q = 0; q < 4; q++) S[b][q] = 0.f;

            #pragma unroll
            for (int s4 = 0; s4 < 4; s4++) {
                int bch = 2 * s4 + (sub & 1);
                #pragma unroll
                for (int jp = 0; jp < 4; jp++) {
                    int row = rbase + jp * 16 + (sub >> 1) * 8 + rin;
                    uint32_t off = row * 128 + ((bch ^ (row & 7)) << 4);
                    uint32_t kh[4];
                    ldsm_x4(kh, stb + AT_KH + off);
                    mma_f16(S[2*jp],   Qh[s4], kh);
                    mma_f16(S[2*jp+1], Qh[s4], kh + 2);
                }
            }

            float mx0 = -1e30f, mx1 = -1e30f;
            #pragma unroll
            for (int b = 0; b < 8; b++) {
                #pragma unroll
                for (int q = 0; q < 4; q++) S[b][q] *= SCALE;
                mx0 = fmaxf(mx0, fmaxf(S[b][0], S[b][1]));
                mx1 = fmaxf(mx1, fmaxf(S[b][2], S[b][3]));
            }
            #pragma unroll
            for (int off = 1; off < 4; off <<= 1) {
                mx0 = fmaxf(mx0, __shfl_xor_sync(0xffffffffu, mx0, off));
                mx1 = fmaxf(mx1, __shfl_xor_sync(0xffffffffu, mx1, off));
            }
            float mn0 = fmaxf(m0, mx0), mn1 = fmaxf(m1, mx1);
            float al0 = __expf(m0 - mn0), al1 = __expf(m1 - mn1);
            m0 = mn0; m1 = mn1;

            float rs0 = 0.f, rs1 = 0.f;
            #pragma unroll
            for (int b = 0; b < 8; b++) {
                S[b][0] = __expf(S[b][0] - mn0); rs0 += S[b][0];
                S[b][1] = __expf(S[b][1] - mn0); rs0 += S[b][1];
                S[b][2] = __expf(S[b][2] - mn1); rs1 += S[b][2];
                S[b][3] = __expf(S[b][3] - mn1); rs1 += S[b][3];
            }
            #pragma unroll
            for (int off = 1; off < 4; off <<= 1) {
                rs0 += __shfl_xor_sync(0xffffffffu, rs0, off);
                rs1 += __shfl_xor_sync(0xffffffffu, rs1, off);
            }
            l0 = l0 * al0 + rs0;
            l1 = l1 * al1 + rs1;
            #pragma unroll
            for (int b = 0; b < 8; b++) {
                O[b][0] *= al0; O[b][1] *= al0;
                O[b][2] *= al1; O[b][3] *= al1;
            }

            // O += Ph Vh
            #pragma unroll
            for (int a = 0; a < 4; a++) {
                uint32_t Ph[4];
                Ph[0] = pack_f16(S[2*a][0],   S[2*a][1]);
                Ph[1] = pack_f16(S[2*a][2],   S[2*a][3]);
                Ph[2] = pack_f16(S[2*a+1][0], S[2*a+1][1]);
                Ph[3] = pack_f16(S[2*a+1][2], S[2*a+1][3]);

                int vrow = rbase + a * 16 + (sub & 1) * 8 + rin;
                #pragma unroll
                for (int bp = 0; bp < 4; bp++) {
                    int ch = 2 * bp + (sub >> 1);
                    uint32_t off = vrow * 128 + ((ch ^ (vrow & 7)) << 4);
                    uint32_t vh[4];
                    ldsm_x4_t(vh, stb + AT_VH + off);
                    mma_f16(O[2*bp],   Ph, vh);
                    mma_f16(O[2*bp+1], Ph, vh + 2);
                }
            }
        }
        __syncthreads();
        if (jt + 2 < SEQ / 128) load_kv(s, jt + 2);
    }

    float inv0 = 1.f / l0, inv1 = 1.f / l1;
    size_t t0 = tok0 + qt * 128 + warp * 16 + g;
    size_t t1 = t0 + 8;
    #pragma unroll
    for (int b = 0; b < 8; b++) {
        int col = head * HDIM + b * 8 + 2 * t;
        *(uint32_t*)&ohi[t0 * DIM + col] = pack_f16(O[b][0] * inv0, O[b][1] * inv0);
        *(uint32_t*)&ohi[t1 * DIM + col] = pack_f16(O[b][2] * inv1, O[b][3] * inv1);
    }
}

// ----------------------------------------------------------------------------
// Launch
// ----------------------------------------------------------------------------
extern "C" void kernel_launch(void* const* d_in, const int* in_sizes, int n_in,
                              void* d_out, int out_size)
{
    const float* x     = (const float*)d_in[0];
    const float* w_qkv = (const float*)d_in[1];
    const float* w_out = (const float*)d_in[2];
    const float* b_out = (const float*)d_in[3];
    float* out = (float*)d_out;

    void *p_xhi, *p_w1hi, *p_w2hi, *p_qh, *p_ahi;
    cudaGetSymbolAddress(&p_xhi, g_xhi);
    cudaGetSymbolAddress(&p_w1hi, g_w1hi);
    cudaGetSymbolAddress(&p_w2hi, g_w2hi);
    cudaGetSymbolAddress(&p_qh, g_qkvhi);
    cudaGetSymbolAddress(&p_ahi, g_ahi);

    cudaFuncSetAttribute(gemm_mma<0>, cudaFuncAttributeMaxDynamicSharedMemorySize, GEMM_SMEM);
    cudaFuncSetAttribute(gemm_mma<2>, cudaFuncAttributeMaxDynamicSharedMemorySize, GEMM_SMEM);
    cudaFuncSetAttribute(attn_mma,    cudaFuncAttributeMaxDynamicSharedMemorySize, AT_SMEM);

    // 0) casts: x -> fp16; w_qkv^T -> fp16; w_out^T -> fp16
    cast_kernel<<<(TOKENS * DIM / 4 + 255) / 256, 256>>>(
        x, (__half*)p_xhi, TOKENS * DIM / 4);
    castT_kernel<<<dim3(QKVDIM / 32, DIM / 32), 256>>>(
        w_qkv, (__half*)p_w1hi, DIM, QKVDIM);
    castT_kernel<<<dim3(DIM / 32, DIM / 32), 256>>>(
        w_out, (__half*)p_w2hi, DIM, DIM);

    // 1) qkv = x @ w_qkv -> fp16 (1-pass, 128x256 tile)     [8192, 3072]
    gemm_mma<2><<<dim3(QKVDIM / 256, TOKENS / 128), 256, GEMM_SMEM>>>(
        (const __half*)p_xhi, (const __half*)p_w1hi,
        nullptr, nullptr, (__half*)p_qh, QKVDIM);

    // 2) attention -> fp16 (KV stage 128)                    [8192, 1024]
    attn_mma<<<dim3(SEQ / 128, HEADS, BATCH), 256, AT_SMEM>>>(
        (const __half*)p_qh, (__half*)p_ahi);

    // 3) out = attn @ w_out + b (1-pass, 128x256 tile)       [8192, 1024]
    gemm_mma<0><<<dim3(DIM / 256, TOKENS / 128), 256, GEMM_SMEM>>>(
        (const __half*)p_ahi, (const __half*)p_w2hi,
        b_out, out, nullptr, DIM);
}

// round 15
// speedup vs baseline: 1.0725x; 1.0725x over previous
#include <cuda_runtime.h>
#include <cuda_fp16.h>
#include <cstdint>

// Problem constants
#define BATCH  8
#define SEQ    1024
#define DIM    1024
#define HEADS  16
#define HDIM   64
#define TOKENS (BATCH * SEQ)          // 8192
#define QKVDIM (3 * DIM)              // 3072
#define SCALE  0.03125f               // 1024^-0.5

// ---------------------------------------------------------------------------
// Scratch (device globals: allocation-guard safe)
// ---------------------------------------------------------------------------
__device__ __half g_xhi[(size_t)TOKENS * DIM];
__device__ __half g_w1hi[(size_t)QKVDIM * DIM];      // w_qkv^T [3072][1024]
__device__ __half g_w2hi[(size_t)DIM * DIM];         // w_out^T [1024][1024]
__device__ __half g_qkvhi[(size_t)TOKENS * QKVDIM];  // qkv [8192][3072]
__device__ __half g_ahi[(size_t)TOKENS * DIM];

// ---------------------------------------------------------------------------
// Helpers
// ---------------------------------------------------------------------------
__device__ __forceinline__ uint32_t smem_u32(const void* p) {
    uint32_t a;
    asm("{ .reg .u64 t; cvta.to.shared.u64 t, %1; cvt.u32.u64 %0, t; }" : "=r"(a) : "l"(p));
    return a;
}

__device__ __forceinline__ void cp_async16(uint32_t dst, const void* src) {
    asm volatile("cp.async.cg.shared.global [%0], [%1], 16;\n" :: "r"(dst), "l"(src));
}
#define CP_COMMIT() asm volatile("cp.async.commit_group;\n" ::: "memory")
#define CP_WAIT2()  asm volatile("cp.async.wait_group 2;\n" ::: "memory")
#define CP_WAIT1()  asm volatile("cp.async.wait_group 1;\n" ::: "memory")
#define CP_WAIT0()  asm volatile("cp.async.wait_group 0;\n" ::: "memory")

__device__ __forceinline__ void ldsm_x4(uint32_t* r, uint32_t addr) {
    asm volatile("ldmatrix.sync.aligned.m8n8.x4.shared.b16 {%0,%1,%2,%3}, [%4];"
                 : "=r"(r[0]), "=r"(r[1]), "=r"(r[2]), "=r"(r[3]) : "r"(addr));
}

__device__ __forceinline__ void ldsm_x4_t(uint32_t* r, uint32_t addr) {
    asm volatile("ldmatrix.sync.aligned.m8n8.x4.trans.shared.b16 {%0,%1,%2,%3}, [%4];"
                 : "=r"(r[0]), "=r"(r[1]), "=r"(r[2]), "=r"(r[3]) : "r"(addr));
}

// fp16 HMMA, fp32 accumulate
__device__ __forceinline__ void mma_f16(float* d, const uint32_t* a, const uint32_t* b) {
    asm volatile("mma.sync.aligned.m16n8k16.row.col.f32.f16.f16.f32 "
                 "{%0,%1,%2,%3}, {%4,%5,%6,%7}, {%8,%9}, {%0,%1,%2,%3};"
                 : "+f"(d[0]), "+f"(d[1]), "+f"(d[2]), "+f"(d[3])
                 : "r"(a[0]), "r"(a[1]), "r"(a[2]), "r"(a[3]), "r"(b[0]), "r"(b[1]));
}

// pack two fp32 into f16x2 (lo -> low half)
__device__ __forceinline__ uint32_t pack_f16(float lo, float hi) {
    uint32_t d;
    asm("cvt.rn.f16x2.f32 %0, %1, %2;" : "=r"(d) : "f"(hi), "f"(lo));
    return d;
}

// ---------------------------------------------------------------------------
// Pure fp16 HMMA GEMM (1-pass): C = A[M,K] @ W[N,K]^T
// OUT==0: write fp32 C (+bias).  OUT==2: fp16.
// Block 128x128, BK=64, 256 threads, 2 CTAs/SM, 3-stage cp.async pipeline,
// XOR-swizzled 128B-row smem. Prefetch issued BEFORE mma work each iter.
// ---------------------------------------------------------------------------
#define GK     1024
#define BK     64
#define NITER  (GK / BK)               // 16
#define TILEB  (128 * 128)             // 16 KB: [128 rows][64 f16 = 128B]
#define STAGEB (2 * TILEB)             // 32 KB (A, W)
#define NSTAGE 3
#define GEMM_SMEM (NSTAGE * STAGEB)    // 96 KB

template<int OUT>
__global__ __launch_bounds__(256, 2) void gemm_mma(
    const __half* __restrict__ Ahi,
    const __half* __restrict__ Whi,
    const float* __restrict__ bias, float* __restrict__ C,
    __half* __restrict__ Chi, int N)
{
    extern __shared__ char sm[];
    const uint32_t sbase = smem_u32(sm);
    const int tid  = threadIdx.x;
    const int lane = tid & 31;
    const int warp = tid >> 5;
    const int wm = warp & 1;
    const int wn = warp >> 1;
    const int m0 = blockIdx.y * 128;
    const int n0 = blockIdx.x * 128;

    float acc[4][4][4];
    #pragma unroll
    for (int i = 0; i < 4; i++)
        #pragma unroll
        for (int j = 0; j < 4; j++)
            #pragma unroll
            for (int q = 0; q < 4; q++) acc[i][j][q] = 0.f;

    auto soff = [&](int s, int t) -> uint32_t { return sbase + s * STAGEB + t * TILEB; };

    auto load_stage = [&](int s, int k0) {
        const __half* gsrc[2] = {Ahi + (size_t)m0 * GK + k0,
                                 Whi + (size_t)n0 * GK + k0};
        #pragma unroll
        for (int t = 0; t < 2; t++) {
            const char* gp = (const char*)gsrc[t];
            #pragma unroll
            for (int j = 0; j < 4; j++) {
                int id = tid + j * 256;           // 0..1023
                int r = id >> 3, c = id & 7;
                uint32_t sw = r * 128 + ((c ^ (r & 7)) << 4);
                cp_async16(soff(s, t) + sw, gp + (size_t)r * (GK * 2) + c * 16);
            }
        }
        CP_COMMIT();
    };

    load_stage(0, 0);
    load_stage(1, BK);

    const int sub = lane >> 3, rin = lane & 7;
    const int a_row_off = (sub & 1) * 8 + rin;
    const int a_chunk   = sub >> 1;
    const int b_row_off = (sub >> 1) * 8 + rin;
    const int b_chunk   = sub & 1;

    for (int it = 0; it < NITER; it++) {
        const int s = it % NSTAGE;
        if (it == NITER - 1) { CP_WAIT0(); } else { CP_WAIT1(); }
        __syncthreads();

        // Prefetch FIRST: overlap global-load issue + smem fill with the mmas
        if (it + 2 < NITER) load_stage((it + 2) % NSTAGE, (it + 2) * BK);

        const uint32_t aH = soff(s, 0), wH = soff(s, 1);

        #pragma unroll
        for (int ks = 0; ks < 4; ks++) {          // 4 k16 steps per BK=64
            uint32_t Ah[4][4], Bh[4][2];

            #pragma unroll
            for (int mi = 0; mi < 4; mi++) {
                int row = wm * 64 + mi * 16 + a_row_off;
                int ch = ks * 2 + a_chunk;
                uint32_t off = row * 128 + ((ch ^ (row & 7)) << 4);
                ldsm_x4(Ah[mi], aH + off);
            }
            #pragma unroll
            for (int p = 0; p < 2; p++) {
                int row = wn * 32 + p * 16 + b_row_off;
                int ch = ks * 2 + b_chunk;
                uint32_t off = row * 128 + ((ch ^ (row & 7)) << 4);
                uint32_t t0[4];
                ldsm_x4(t0, wH + off);
                Bh[p*2  ][0] = t0[0]; Bh[p*2  ][1] = t0[1];
                Bh[p*2+1][0] = t0[2]; Bh[p*2+1][1] = t0[3];
            }

            #pragma unroll
            for (int mi = 0; mi < 4; mi++)
                #pragma unroll
                for (int ni = 0; ni < 4; ni++)
                    mma_f16(acc[mi][ni], Ah[mi], Bh[ni]);
        }
    }

    const int g = lane >> 2, c2 = (lane & 3) * 2;
    #pragma unroll
    for (int mi = 0; mi < 4; mi++) {
        int row = m0 + wm * 64 + mi * 16 + g;
        #pragma unroll
        for (int ni = 0; ni < 4; ni++) {
            int col = n0 + wn * 32 + ni * 8 + c2;
            if (OUT == 0) {
                float b0 = 0.f, b1 = 0.f;
                if (bias) { b0 = bias[col]; b1 = bias[col + 1]; }
                float2 v0 = make_float2(acc[mi][ni][0] + b0, acc[mi][ni][1] + b1);
                float2 v1 = make_float2(acc[mi][ni][2] + b0, acc[mi][ni][3] + b1);
                *(float2*)&C[(size_t)row * N + col] = v0;
                *(float2*)&C[(size_t)(row + 8) * N + col] = v1;
            } else {
                *(uint32_t*)&Chi[(size_t)row * N + col] =
                    pack_f16(acc[mi][ni][0], acc[mi][ni][1]);
                *(uint32_t*)&Chi[(size_t)(row + 8) * N + col] =
                    pack_f16(acc[mi][ni][2], acc[mi][ni][3]);
            }
        }
    }
}

// ---------------------------------------------------------------------------
// fp32 -> fp16 cast (elementwise, float4)
// ---------------------------------------------------------------------------
__global__ __launch_bounds__(256) void cast_kernel(
    const float* __restrict__ in, __half* __restrict__ hi, int n4)
{
    int i = blockIdx.x * blockDim.x + threadIdx.x;
    if (i >= n4) return;
    float4 v = ((const float4*)in)[i];
    ((uint2*)hi)[i] = make_uint2(pack_f16(v.x, v.y), pack_f16(v.z, v.w));
}

// ---------------------------------------------------------------------------
// fp32 [K][N] -> transposed fp16 [N][K]
// ---------------------------------------------------------------------------
__global__ __launch_bounds__(256) void castT_kernel(
    const float* __restrict__ w, __half* __restrict__ thi, int K, int N)
{
    __shared__ float t[32][33];
    const int n0 = blockIdx.x * 32, k0 = blockIdx.y * 32;
    const int tx = threadIdx.x & 31, ty = threadIdx.x >> 5;
    #pragma unroll
    for (int j = ty; j < 32; j += 8)
        t[j][tx] = w[(size_t)(k0 + j) * N + n0 + tx];
    __syncthreads();
    #pragma unroll
    for (int j = ty; j < 32; j += 8)
        thi[(size_t)(n0 + j) * K + k0 + tx] = __float2half_rn(t[tx][j]);
}

// ---------------------------------------------------------------------------
// HMMA flash attention, pure fp16 (S = Qh Kh^T; O += Ph Vh).
// KV stage = 64 keys, double-buffered; 2 CTAs/SM, 48 KB smem each.
// Prefetch issued before compute each tile.
// ---------------------------------------------------------------------------
#define AT_Q    0
#define AT_ST   16384
#define AT_STB  16384
#define AT_KH   0
#define AT_VH   8192
#define AT_SMEM (AT_ST + 2 * AT_STB)   // 49152

__global__ __launch_bounds__(256, 2) void attn_mma(
    const __half* __restrict__ qh, __half* __restrict__ ohi)
{
    extern __shared__ char sm[];
    const uint32_t sb = smem_u32(sm);
    const int tid  = threadIdx.x;
    const int lane = tid & 31;
    const int warp = tid >> 5;
    const int sub = lane >> 3, rin = lane & 7;
    const int g = lane >> 2, t = lane & 3;

    const int qt = blockIdx.x, head = blockIdx.y, batch = blockIdx.z;
    const size_t tok0 = (size_t)batch * SEQ;
    const size_t qbase = (tok0 + qt * 128) * QKVDIM + head * HDIM;

    #pragma unroll
    for (int j = 0; j < 4; j++) {
        int id = tid + j * 256;
        int r = id >> 3, c = id & 7;
        uint32_t sw = r * 128 + ((c ^ (r & 7)) << 4);
        cp_async16(sb + AT_Q + sw, (const char*)(qh + qbase) + (size_t)r * QKVDIM * 2 + c * 16);
    }
    CP_COMMIT();

    auto load_kv = [&](int s, int jt) {
        size_t kb = (tok0 + jt * 64) * QKVDIM + DIM + head * HDIM;
        size_t vb = kb + DIM;
        uint32_t st = sb + AT_ST + s * AT_STB;
        #pragma unroll
        for (int j = 0; j < 2; j++) {
            int id = tid + j * 256;
            int r = id >> 3, c = id & 7;
            uint32_t sw = r * 128 + ((c ^ (r & 7)) << 4);
            size_t go = (size_t)r * QKVDIM * 2 + c * 16;
            cp_async16(st + AT_KH + sw, (const char*)(qh + kb) + go);
            cp_async16(st + AT_VH + sw, (const char*)(qh + vb) + go);
        }
        CP_COMMIT();
    };

    load_kv(0, 0);
    load_kv(1, 1);

    CP_WAIT2();
    __syncthreads();
    uint32_t Qh[4][4];
    {
        int row = warp * 16 + (sub & 1) * 8 + rin;
        #pragma unroll
        for (int s4 = 0; s4 < 4; s4++) {
            int ch = 2 * s4 + (sub >> 1);
            uint32_t off = row * 128 + ((ch ^ (row & 7)) << 4);
            ldsm_x4(Qh[s4], sb + AT_Q + off);
        }
    }

    float m0 = -1e30f, m1 = -1e30f, l0 = 0.f, l1 = 0.f;
    float O[8][4];
    #pragma unroll
    for (int b = 0; b < 8; b++)
        #pragma unroll
        for (int q = 0; q < 4; q++) O[b][q] = 0.f;

    for (int jt = 0; jt < SEQ / 64; jt++) {
        const int s = jt & 1;
        if (jt == SEQ / 64 - 1) { CP_WAIT0(); } else { CP_WAIT1(); }
        __syncthreads();

        // Prefetch first: overlap KV global loads with this tile's compute.
        // Stage s was fully consumed before the barrier above (2-stage ring),
        // but we write stage s for tile jt+2 — still consumed only at jt+2,
        // so ordering is: stage s read finished at jt-? ... stage s holds jt,
        // being read NOW. Must NOT overwrite: prefetch targets stage s of
        // tile jt+2 == same buffer as jt. So prefetch must come AFTER compute
        // for the 2-stage ring — keep it after compute (unchanged) here.
        const uint32_t stb = sb + AT_ST + s * AT_STB;

        float S[8][4];
        #pragma unroll
        for (int b = 0; b < 8; b++)
            #pragma unroll
            for (int q = 0; q < 4; q++) S[b][q] = 0.f;

        #pragma unroll
        for (int s4 = 0; s4 < 4; s4++) {
            int bch = 2 * s4 + (sub & 1);
            #pragma unroll
            for (int jp = 0; jp < 4; jp++) {
                int row = jp * 16 + (sub >> 1) * 8 + rin;
                uint32_t off = row * 128 + ((bch ^ (row & 7)) << 4);
                uint32_t kh[4];
                ldsm_x4(kh, stb + AT_KH + off);
                mma_f16(S[2*jp],   Qh[s4], kh);
                mma_f16(S[2*jp+1], Qh[s4], kh + 2);
            }
        }

        float mx0 = -1e30f, mx1 = -1e30f;
        #pragma unroll
        for (int b = 0; b < 8; b++) {
            #pragma unroll
            for (int q = 0; q < 4; q++) S[b][q] *= SCALE;
            mx0 = fmaxf(mx0, fmaxf(S[b][0], S[b][1]));
            mx1 = fmaxf(mx1, fmaxf(S[b][2], S[b][3]));
        }
        #pragma unroll
        for (int off = 1; off < 4; off <<= 1) {
            mx0 = fmaxf(mx0, __shfl_xor_sync(0xffffffffu, mx0, off));
            mx1 = fmaxf(mx1, __shfl_xor_sync(0xffffffffu, mx1, off));
        }
        float mn0 = fmaxf(m0, mx0), mn1 = fmaxf(m1, mx1);
        float al0 = __expf(m0 - mn0), al1 = __expf(m1 - mn1);
        m0 = mn0; m1 = mn1;

        float rs0 = 0.f, rs1 = 0.f;
        #pragma unroll
        for (int b = 0; b < 8; b++) {
            S[b][0] = __expf(S[b][0] - mn0); rs0 += S[b][0];
            S[b][1] = __expf(S[b][1] - mn0); rs0 += S[b][1];
            S[b][2] = __expf(S[b][2] - mn1); rs1 += S[b][2];
            S[b][3] = __expf(S[b][3] - mn1); rs1 += S[b][3];
        }
        #pragma unroll
        for (int off = 1; off < 4; off <<= 1) {
            rs0 += __shfl_xor_sync(0xffffffffu, rs0, off);
            rs1 += __shfl_xor_sync(0xffffffffu, rs1, off);
        }
        l0 = l0 * al0 + rs0;
        l1 = l1 * al1 + rs1;
        #pragma unroll
        for (int b = 0; b < 8; b++) {
            O[b][0] *= al0; O[b][1] *= al0;
            O[b][2] *= al1; O[b][3] *= al1;
        }

        // O += Ph Vh (1-pass)
        #pragma unroll
        for (int a = 0; a < 4; a++) {
            uint32_t Ph[4];
            Ph[0] = pack_f16(S[2*a][0],   S[2*a][1]);
            Ph[1] = pack_f16(S[2*a][2],   S[2*a][3]);
            Ph[2] = pack_f16(S[2*a+1][0], S[2*a+1][1]);
            Ph[3] = pack_f16(S[2*a+1][2], S[2*a+1][3]);

            int vrow = a * 16 + (sub & 1) * 8 + rin;
            #pragma unroll
            for (int bp = 0; bp < 4; bp++) {
                int ch = 2 * bp + (sub >> 1);
                uint32_t off = vrow * 128 + ((ch ^ (vrow & 7)) << 4);
                uint32_t vh[4];
                ldsm_x4_t(vh, stb + AT_VH + off);
                mma_f16(O[2*bp],   Ph, vh);
                mma_f16(O[2*bp+1], Ph, vh + 2);
            }
        }
        __syncthreads();
        if (jt + 2 < SEQ / 64) load_kv(s, jt + 2);
    }

    float inv0 = 1.f / l0, inv1 = 1.f / l1;
    size_t t0 = tok0 + qt * 128 + warp * 16 + g;
    size_t t1 = t0 + 8;
    #pragma unroll
    for (int b = 0; b < 8; b++) {
        int col = head * HDIM + b * 8 + 2 * t;
        *(uint32_t*)&ohi[t0 * DIM + col] = pack_f16(O[b][0] * inv0, O[b][1] * inv0);
        *(uint32_t*)&ohi[t1 * DIM + col] = pack_f16(O[b][2] * inv1, O[b][3] * inv1);
    }
}

// ----------------------------------------------------------------------------
// Launch
// ----------------------------------------------------------------------------
extern "C" void kernel_launch(void* const* d_in, const int* in_sizes, int n_in,
                              void* d_out, int out_size)
{
    const float* x     = (const float*)d_in[0];
    const float* w_qkv = (const float*)d_in[1];
    const float* w_out = (const float*)d_in[2];
    const float* b_out = (const float*)d_in[3];
    float* out = (float*)d_out;

    void *p_xhi, *p_w1hi, *p_w2hi, *p_qh, *p_ahi;
    cudaGetSymbolAddress(&p_xhi, g_xhi);
    cudaGetSymbolAddress(&p_w1hi, g_w1hi);
    cudaGetSymbolAddress(&p_w2hi, g_w2hi);
    cudaGetSymbolAddress(&p_qh, g_qkvhi);
    cudaGetSymbolAddress(&p_ahi, g_ahi);

    cudaFuncSetAttribute(gemm_mma<0>, cudaFuncAttributeMaxDynamicSharedMemorySize, GEMM_SMEM);
    cudaFuncSetAttribute(gemm_mma<2>, cudaFuncAttributeMaxDynamicSharedMemorySize, GEMM_SMEM);
    cudaFuncSetAttribute(attn_mma,    cudaFuncAttributeMaxDynamicSharedMemorySize, AT_SMEM);

    // 0) casts: x -> fp16; w_qkv^T -> fp16; w_out^T -> fp16
    cast_kernel<<<(TOKENS * DIM / 4 + 255) / 256, 256>>>(
        x, (__half*)p_xhi, TOKENS * DIM / 4);
    castT_kernel<<<dim3(QKVDIM / 32, DIM / 32), 256>>>(
        w_qkv, (__half*)p_w1hi, DIM, QKVDIM);
    castT_kernel<<<dim3(DIM / 32, DIM / 32), 256>>>(
        w_out, (__half*)p_w2hi, DIM, DIM);

    // 1) qkv = x @ w_qkv -> fp16 (1-pass, BK=64)            [8192, 3072]
    gemm_mma<2><<<dim3(QKVDIM / 128, TOKENS / 128), 256, GEMM_SMEM>>>(
        (const __half*)p_xhi, (const __half*)p_w1hi,
        nullptr, nullptr, (__half*)p_qh, QKVDIM);

    // 2) attention -> fp16 (pure 1-pass)                     [8192, 1024]
    attn_mma<<<dim3(SEQ / 128, HEADS, BATCH), 256, AT_SMEM>>>(
        (const __half*)p_qh, (__half*)p_ahi);

    // 3) out = attn @ w_out + b (1-pass, BK=64)              [8192, 1024]
    gemm_mma<0><<<dim3(DIM / 128, TOKENS / 128), 256, GEMM_SMEM>>>(
        (const __half*)p_ahi, (const __half*)p_w2hi,
        b_out, out, nullptr, DIM);
}

// round 16
// speedup vs baseline: 1.1072x; 1.0324x over previous
#include <cuda_runtime.h>
#include <cuda_fp16.h>
#include <cstdint>

// Problem constants
#define BATCH  8
#define SEQ    1024
#define DIM    1024
#define HEADS  16
#define HDIM   64
#define TOKENS (BATCH * SEQ)          // 8192
#define QKVDIM (3 * DIM)              // 3072
#define SCALE  0.03125f               // 1024^-0.5
#define SCALE2 (0.03125f * 1.44269504f)  // SCALE * log2(e) for exp2 softmax

// ---------------------------------------------------------------------------
// Scratch (device globals: allocation-guard safe)
// ---------------------------------------------------------------------------
__device__ __half g_xhi[(size_t)TOKENS * DIM];
__device__ __half g_w1hi[(size_t)QKVDIM * DIM];      // w_qkv^T [3072][1024]
__device__ __half g_w2hi[(size_t)DIM * DIM];         // w_out^T [1024][1024]
__device__ __half g_qkvhi[(size_t)TOKENS * QKVDIM];  // qkv [8192][3072]
__device__ __half g_ahi[(size_t)TOKENS * DIM];

// ---------------------------------------------------------------------------
// Helpers
// ---------------------------------------------------------------------------
__device__ __forceinline__ uint32_t smem_u32(const void* p) {
    uint32_t a;
    asm("{ .reg .u64 t; cvta.to.shared.u64 t, %1; cvt.u32.u64 %0, t; }" : "=r"(a) : "l"(p));
    return a;
}

__device__ __forceinline__ void cp_async16(uint32_t dst, const void* src) {
    asm volatile("cp.async.cg.shared.global [%0], [%1], 16;\n" :: "r"(dst), "l"(src));
}
#define CP_COMMIT() asm volatile("cp.async.commit_group;\n" ::: "memory")
#define CP_WAIT2()  asm volatile("cp.async.wait_group 2;\n" ::: "memory")
#define CP_WAIT1()  asm volatile("cp.async.wait_group 1;\n" ::: "memory")
#define CP_WAIT0()  asm volatile("cp.async.wait_group 0;\n" ::: "memory")

__device__ __forceinline__ void ldsm_x4(uint32_t* r, uint32_t addr) {
    asm volatile("ldmatrix.sync.aligned.m8n8.x4.shared.b16 {%0,%1,%2,%3}, [%4];"
                 : "=r"(r[0]), "=r"(r[1]), "=r"(r[2]), "=r"(r[3]) : "r"(addr));
}

__device__ __forceinline__ void ldsm_x4_t(uint32_t* r, uint32_t addr) {
    asm volatile("ldmatrix.sync.aligned.m8n8.x4.trans.shared.b16 {%0,%1,%2,%3}, [%4];"
                 : "=r"(r[0]), "=r"(r[1]), "=r"(r[2]), "=r"(r[3]) : "r"(addr));
}

// fp16 HMMA, fp32 accumulate
__device__ __forceinline__ void mma_f16(float* d, const uint32_t* a, const uint32_t* b) {
    asm volatile("mma.sync.aligned.m16n8k16.row.col.f32.f16.f16.f32 "
                 "{%0,%1,%2,%3}, {%4,%5,%6,%7}, {%8,%9}, {%0,%1,%2,%3};"
                 : "+f"(d[0]), "+f"(d[1]), "+f"(d[2]), "+f"(d[3])
                 : "r"(a[0]), "r"(a[1]), "r"(a[2]), "r"(a[3]), "r"(b[0]), "r"(b[1]));
}

// pack two fp32 into f16x2 (lo -> low half)
__device__ __forceinline__ uint32_t pack_f16(float lo, float hi) {
    uint32_t d;
    asm("cvt.rn.f16x2.f32 %0, %1, %2;" : "=r"(d) : "f"(hi), "f"(lo));
    return d;
}

// ---------------------------------------------------------------------------
// Pure fp16 HMMA GEMM (1-pass): C = A[M,K] @ W[N,K]^T   (R13 verbatim)
// OUT==0: write fp32 C (+bias).  OUT==2: fp16.
// Block 128x128, BK=64, 256 threads, 2 CTAs/SM, 3-stage cp.async pipeline,
// XOR-swizzled 128B-row smem. Prefetch after compute (R13 ordering).
// ---------------------------------------------------------------------------
#define GK     1024
#define BK     64
#define NITER  (GK / BK)               // 16
#define TILEB  (128 * 128)             // 16 KB: [128 rows][64 f16 = 128B]
#define STAGEB (2 * TILEB)             // 32 KB (A, W)
#define NSTAGE 3
#define GEMM_SMEM (NSTAGE * STAGEB)    // 96 KB

template<int OUT>
__global__ __launch_bounds__(256, 2) void gemm_mma(
    const __half* __restrict__ Ahi,
    const __half* __restrict__ Whi,
    const float* __restrict__ bias, float* __restrict__ C,
    __half* __restrict__ Chi, int N)
{
    extern __shared__ char sm[];
    const uint32_t sbase = smem_u32(sm);
    const int tid  = threadIdx.x;
    const int lane = tid & 31;
    const int warp = tid >> 5;
    const int wm = warp & 1;
    const int wn = warp >> 1;
    const int m0 = blockIdx.y * 128;
    const int n0 = blockIdx.x * 128;

    float acc[4][4][4];
    #pragma unroll
    for (int i = 0; i < 4; i++)
        #pragma unroll
        for (int j = 0; j < 4; j++)
            #pragma unroll
            for (int q = 0; q < 4; q++) acc[i][j][q] = 0.f;

    auto soff = [&](int s, int t) -> uint32_t { return sbase + s * STAGEB + t * TILEB; };

    auto load_stage = [&](int s, int k0) {
        const __half* gsrc[2] = {Ahi + (size_t)m0 * GK + k0,
                                 Whi + (size_t)n0 * GK + k0};
        #pragma unroll
        for (int t = 0; t < 2; t++) {
            const char* gp = (const char*)gsrc[t];
            #pragma unroll
            for (int j = 0; j < 4; j++) {
                int id = tid + j * 256;           // 0..1023
                int r = id >> 3, c = id & 7;
                uint32_t sw = r * 128 + ((c ^ (r & 7)) << 4);
                cp_async16(soff(s, t) + sw, gp + (size_t)r * (GK * 2) + c * 16);
            }
        }
        CP_COMMIT();
    };

    load_stage(0, 0);
    load_stage(1, BK);

    const int sub = lane >> 3, rin = lane & 7;
    const int a_row_off = (sub & 1) * 8 + rin;
    const int a_chunk   = sub >> 1;
    const int b_row_off = (sub >> 1) * 8 + rin;
    const int b_chunk   = sub & 1;

    for (int it = 0; it < NITER; it++) {
        const int s = it % NSTAGE;
        if (it == NITER - 1) { CP_WAIT0(); } else { CP_WAIT1(); }
        __syncthreads();

        const uint32_t aH = soff(s, 0), wH = soff(s, 1);

        #pragma unroll
        for (int ks = 0; ks < 4; ks++) {          // 4 k16 steps per BK=64
            uint32_t Ah[4][4], Bh[4][2];

            #pragma unroll
            for (int mi = 0; mi < 4; mi++) {
                int row = wm * 64 + mi * 16 + a_row_off;
                int ch = ks * 2 + a_chunk;
                uint32_t off = row * 128 + ((ch ^ (row & 7)) << 4);
                ldsm_x4(Ah[mi], aH + off);
            }
            #pragma unroll
            for (int p = 0; p < 2; p++) {
                int row = wn * 32 + p * 16 + b_row_off;
                int ch = ks * 2 + b_chunk;
                uint32_t off = row * 128 + ((ch ^ (row & 7)) << 4);
                uint32_t t0[4];
                ldsm_x4(t0, wH + off);
                Bh[p*2  ][0] = t0[0]; Bh[p*2  ][1] = t0[1];
                Bh[p*2+1][0] = t0[2]; Bh[p*2+1][1] = t0[3];
            }

            #pragma unroll
            for (int mi = 0; mi < 4; mi++)
                #pragma unroll
                for (int ni = 0; ni < 4; ni++)
                    mma_f16(acc[mi][ni], Ah[mi], Bh[ni]);
        }
        if (it + 2 < NITER) load_stage((it + 2) % NSTAGE, (it + 2) * BK);
    }

    const int g = lane >> 2, c2 = (lane & 3) * 2;
    #pragma unroll
    for (int mi = 0; mi < 4; mi++) {
        int row = m0 + wm * 64 + mi * 16 + g;
        #pragma unroll
        for (int ni = 0; ni < 4; ni++) {
            int col = n0 + wn * 32 + ni * 8 + c2;
            if (OUT == 0) {
                float b0 = 0.f, b1 = 0.f;
                if (bias) { b0 = bias[col]; b1 = bias[col + 1]; }
                float2 v0 = make_float2(acc[mi][ni][0] + b0, acc[mi][ni][1] + b1);
                float2 v1 = make_float2(acc[mi][ni][2] + b0, acc[mi][ni][3] + b1);
                *(float2*)&C[(size_t)row * N + col] = v0;
                *(float2*)&C[(size_t)(row + 8) * N + col] = v1;
            } else {
                *(uint32_t*)&Chi[(size_t)row * N + col] =
                    pack_f16(acc[mi][ni][0], acc[mi][ni][1]);
                *(uint32_t*)&Chi[(size_t)(row + 8) * N + col] =
                    pack_f16(acc[mi][ni][2], acc[mi][ni][3]);
            }
        }
    }
}

// ---------------------------------------------------------------------------
// fp32 -> fp16 cast (elementwise, float4)
// ---------------------------------------------------------------------------
__global__ __launch_bounds__(256) void cast_kernel(
    const float* __restrict__ in, __half* __restrict__ hi, int n4)
{
    int i = blockIdx.x * blockDim.x + threadIdx.x;
    if (i >= n4) return;
    float4 v = ((const float4*)in)[i];
    ((uint2*)hi)[i] = make_uint2(pack_f16(v.x, v.y), pack_f16(v.z, v.w));
}

// ---------------------------------------------------------------------------
// fp32 [K][N] -> transposed fp16 [N][K]
// ---------------------------------------------------------------------------
__global__ __launch_bounds__(256) void castT_kernel(
    const float* __restrict__ w, __half* __restrict__ thi, int K, int N)
{
    __shared__ float t[32][33];
    const int n0 = blockIdx.x * 32, k0 = blockIdx.y * 32;
    const int tx = threadIdx.x & 31, ty = threadIdx.x >> 5;
    #pragma unroll
    for (int j = ty; j < 32; j += 8)
        t[j][tx] = w[(size_t)(k0 + j) * N + n0 + tx];
    __syncthreads();
    #pragma unroll
    for (int j = ty; j < 32; j += 8)
        thi[(size_t)(n0 + j) * K + k0 + tx] = __float2half_rn(t[tx][j]);
}

// ---------------------------------------------------------------------------
// HMMA flash attention, pure fp16 (S = Qh Kh^T; O += Ph Vh).
// 3-stage KV ring (16 KB/stage) -> trailing barrier removed (one barrier per
// KV tile, R7-style). exp2-domain softmax (log2e folded into SCALE).
// smem: Q 16KB + 3 x 16KB = 64 KB; 2 CTAs/SM.
// ---------------------------------------------------------------------------
#define AT_Q    0
#define AT_ST   16384
#define AT_STB  16384
#define AT_KH   0
#define AT_VH   8192
#define AT_NST  3
#define AT_SMEM (AT_ST + AT_NST * AT_STB)   // 65536

__global__ __launch_bounds__(256, 2) void attn_mma(
    const __half* __restrict__ qh, __half* __restrict__ ohi)
{
    extern __shared__ char sm[];
    const uint32_t sb = smem_u32(sm);
    const int tid  = threadIdx.x;
    const int lane = tid & 31;
    const int warp = tid >> 5;
    const int sub = lane >> 3, rin = lane & 7;
    const int g = lane >> 2, t = lane & 3;

    const int qt = blockIdx.x, head = blockIdx.y, batch = blockIdx.z;
    const size_t tok0 = (size_t)batch * SEQ;
    const size_t qbase = (tok0 + qt * 128) * QKVDIM + head * HDIM;

    #pragma unroll
    for (int j = 0; j < 4; j++) {
        int id = tid + j * 256;
        int r = id >> 3, c = id & 7;
        uint32_t sw = r * 128 + ((c ^ (r & 7)) << 4);
        cp_async16(sb + AT_Q + sw, (const char*)(qh + qbase) + (size_t)r * QKVDIM * 2 + c * 16);
    }
    CP_COMMIT();

    auto load_kv = [&](int s, int jt) {
        size_t kb = (tok0 + jt * 64) * QKVDIM + DIM + head * HDIM;
        size_t vb = kb + DIM;
        uint32_t st = sb + AT_ST + s * AT_STB;
        #pragma unroll
        for (int j = 0; j < 2; j++) {
            int id = tid + j * 256;
            int r = id >> 3, c = id & 7;
            uint32_t sw = r * 128 + ((c ^ (r & 7)) << 4);
            size_t go = (size_t)r * QKVDIM * 2 + c * 16;
            cp_async16(st + AT_KH + sw, (const char*)(qh + kb) + go);
            cp_async16(st + AT_VH + sw, (const char*)(qh + vb) + go);
        }
        CP_COMMIT();
    };

    load_kv(0, 0);
    load_kv(1, 1);

    CP_WAIT2();           // Q group complete (k0, k1 may be pending)
    __syncthreads();
    uint32_t Qh[4][4];
    {
        int row = warp * 16 + (sub & 1) * 8 + rin;
        #pragma unroll
        for (int s4 = 0; s4 < 4; s4++) {
            int ch = 2 * s4 + (sub >> 1);
            uint32_t off = row * 128 + ((ch ^ (row & 7)) << 4);
            ldsm_x4(Qh[s4], sb + AT_Q + off);
        }
    }

    float m0 = -1e30f, m1 = -1e30f, l0 = 0.f, l1 = 0.f;
    float O[8][4];
    #pragma unroll
    for (int b = 0; b < 8; b++)
        #pragma unroll
        for (int q = 0; q < 4; q++) O[b][q] = 0.f;

    const int NT = SEQ / 64;          // 16 KV tiles
    for (int jt = 0; jt < NT; jt++) {
        const int s = jt % AT_NST;
        if (jt == NT - 1) { CP_WAIT0(); } else { CP_WAIT1(); }
        __syncthreads();              // only barrier per tile (3-stage ring)
        const uint32_t stb = sb + AT_ST + s * AT_STB;

        float S[8][4];
        #pragma unroll
        for (int b = 0; b < 8; b++)
            #pragma unroll
            for (int q = 0; q < 4; q++) S[b][q] = 0.f;

        #pragma unroll
        for (int s4 = 0; s4 < 4; s4++) {
            int bch = 2 * s4 + (sub & 1);
            #pragma unroll
            for (int jp = 0; jp < 4; jp++) {
                int row = jp * 16 + (sub >> 1) * 8 + rin;
                uint32_t off = row * 128 + ((bch ^ (row & 7)) << 4);
                uint32_t kh[4];
                ldsm_x4(kh, stb + AT_KH + off);
                mma_f16(S[2*jp],   Qh[s4], kh);
                mma_f16(S[2*jp+1], Qh[s4], kh + 2);
            }
        }

        // exp2-domain online softmax
        float mx0 = -1e30f, mx1 = -1e30f;
        #pragma unroll
        for (int b = 0; b < 8; b++) {
            #pragma unroll
            for (int q = 0; q < 4; q++) S[b][q] *= SCALE2;
            mx0 = fmaxf(mx0, fmaxf(S[b][0], S[b][1]));
            mx1 = fmaxf(mx1, fmaxf(S[b][2], S[b][3]));
        }
        #pragma unroll
        for (int off = 1; off < 4; off <<= 1) {
            mx0 = fmaxf(mx0, __shfl_xor_sync(0xffffffffu, mx0, off));
            mx1 = fmaxf(mx1, __shfl_xor_sync(0xffffffffu, mx1, off));
        }
        float mn0 = fmaxf(m0, mx0), mn1 = fmaxf(m1, mx1);
        float al0 = exp2f(m0 - mn0), al1 = exp2f(m1 - mn1);
        m0 = mn0; m1 = mn1;

        float rs0 = 0.f, rs1 = 0.f;
        #pragma unroll
        for (int b = 0; b < 8; b++) {
            S[b][0] = exp2f(S[b][0] - mn0); rs0 += S[b][0];
            S[b][1] = exp2f(S[b][1] - mn0); rs0 += S[b][1];
            S[b][2] = exp2f(S[b][2] - mn1); rs1 += S[b][2];
            S[b][3] = exp2f(S[b][3] - mn1); rs1 += S[b][3];
        }
        #pragma unroll
        for (int off = 1; off < 4; off <<= 1) {
            rs0 += __shfl_xor_sync(0xffffffffu, rs0, off);
            rs1 += __shfl_xor_sync(0xffffffffu, rs1, off);
        }
        l0 = l0 * al0 + rs0;
        l1 = l1 * al1 + rs1;
        #pragma unroll
        for (int b = 0; b < 8; b++) {
            O[b][0] *= al0; O[b][1] *= al0;
            O[b][2] *= al1; O[b][3] *= al1;
        }

        // O += Ph Vh (1-pass)
        #pragma unroll
        for (int a = 0; a < 4; a++) {
            uint32_t Ph[4];
            Ph[0] = pack_f16(S[2*a][0],   S[2*a][1]);
            Ph[1] = pack_f16(S[2*a][2],   S[2*a][3]);
            Ph[2] = pack_f16(S[2*a+1][0], S[2*a+1][1]);
            Ph[3] = pack_f16(S[2*a+1][2], S[2*a+1][3]);

            int vrow = a * 16 + (sub & 1) * 8 + rin;
            #pragma unroll
            for (int bp = 0; bp < 4; bp++) {
                int ch = 2 * bp + (sub >> 1);
                uint32_t off = vrow * 128 + ((ch ^ (vrow & 7)) << 4);
                uint32_t vh[4];
                ldsm_x4_t(vh, stb + AT_VH + off);
                mma_f16(O[2*bp],   Ph, vh);
                mma_f16(O[2*bp+1], Ph, vh + 2);
            }
        }
        // 3-stage ring: prefetch target (jt+2)%3 was consumed at jt-1 and is
        // protected by the top-of-iter barrier -> no trailing barrier needed.
        if (jt + 2 < NT) load_kv((jt + 2) % AT_NST, jt + 2);
    }

    float inv0 = 1.f / l0, inv1 = 1.f / l1;
    size_t t0 = tok0 + qt * 128 + warp * 16 + g;
    size_t t1 = t0 + 8;
    #pragma unroll
    for (int b = 0; b < 8; b++) {
        int col = head * HDIM + b * 8 + 2 * t;
        *(uint32_t*)&ohi[t0 * DIM + col] = pack_f16(O[b][0] * inv0, O[b][1] * inv0);
        *(uint32_t*)&ohi[t1 * DIM + col] = pack_f16(O[b][2] * inv1, O[b][3] * inv1);
    }
}

// ----------------------------------------------------------------------------
// Launch
// ----------------------------------------------------------------------------
extern "C" void kernel_launch(void* const* d_in, const int* in_sizes, int n_in,
                              void* d_out, int out_size)
{
    const float* x     = (const float*)d_in[0];
    const float* w_qkv = (const float*)d_in[1];
    const float* w_out = (const float*)d_in[2];
    const float* b_out = (const float*)d_in[3];
    float* out = (float*)d_out;

    void *p_xhi, *p_w1hi, *p_w2hi, *p_qh, *p_ahi;
    cudaGetSymbolAddress(&p_xhi, g_xhi);
    cudaGetSymbolAddress(&p_w1hi, g_w1hi);
    cudaGetSymbolAddress(&p_w2hi, g_w2hi);
    cudaGetSymbolAddress(&p_qh, g_qkvhi);
    cudaGetSymbolAddress(&p_ahi, g_ahi);

    cudaFuncSetAttribute(gemm_mma<0>, cudaFuncAttributeMaxDynamicSharedMemorySize, GEMM_SMEM);
    cudaFuncSetAttribute(gemm_mma<2>, cudaFuncAttributeMaxDynamicSharedMemorySize, GEMM_SMEM);
    cudaFuncSetAttribute(attn_mma,    cudaFuncAttributeMaxDynamicSharedMemorySize, AT_SMEM);

    // 0) casts: x -> fp16; w_qkv^T -> fp16; w_out^T -> fp16
    cast_kernel<<<(TOKENS * DIM / 4 + 255) / 256, 256>>>(
        x, (__half*)p_xhi, TOKENS * DIM / 4);
    castT_kernel<<<dim3(QKVDIM / 32, DIM / 32), 256>>>(
        w_qkv, (__half*)p_w1hi, DIM, QKVDIM);
    castT_kernel<<<dim3(DIM / 32, DIM / 32), 256>>>(
        w_out, (__half*)p_w2hi, DIM, DIM);

    // 1) qkv = x @ w_qkv -> fp16 (1-pass, BK=64)            [8192, 3072]
    gemm_mma<2><<<dim3(QKVDIM / 128, TOKENS / 128), 256, GEMM_SMEM>>>(
        (const __half*)p_xhi, (const __half*)p_w1hi,
        nullptr, nullptr, (__half*)p_qh, QKVDIM);

    // 2) attention -> fp16 (3-stage KV ring)                 [8192, 1024]
    attn_mma<<<dim3(SEQ / 128, HEADS, BATCH), 256, AT_SMEM>>>(
        (const __half*)p_qh, (__half*)p_ahi);

    // 3) out = attn @ w_out + b (1-pass, BK=64)              [8192, 1024]
    gemm_mma<0><<<dim3(DIM / 128, TOKENS / 128), 256, GEMM_SMEM>>>(
        (const __half*)p_ahi, (const __half*)p_w2hi,
        b_out, out, nullptr, DIM);
}

// round 17
// speedup vs baseline: 1.1309x; 1.0215x over previous
#include <cuda_runtime.h>
#include <cuda_fp16.h>
#include <cstdint>

// Problem constants
#define BATCH  8
#define SEQ    1024
#define DIM    1024
#define HEADS  16
#define HDIM   64
#define TOKENS (BATCH * SEQ)          // 8192
#define QKVDIM (3 * DIM)              // 3072
#define SCALE  0.03125f               // 1024^-0.5
#define SCALE2 (0.03125f * 1.44269504f)  // SCALE * log2(e) for exp2 softmax

// ---------------------------------------------------------------------------
// Scratch (device globals: allocation-guard safe)
// ---------------------------------------------------------------------------
__device__ __half g_xhi[(size_t)TOKENS * DIM];
__device__ __half g_w1hi[(size_t)QKVDIM * DIM];      // w_qkv^T [3072][1024]
__device__ __half g_w2hi[(size_t)DIM * DIM];         // w_out^T [1024][1024]
__device__ __half g_qkvhi[(size_t)TOKENS * QKVDIM];  // qkv [8192][3072]
__device__ __half g_ahi[(size_t)TOKENS * DIM];

// ---------------------------------------------------------------------------
// Helpers
// ---------------------------------------------------------------------------
__device__ __forceinline__ uint32_t smem_u32(const void* p) {
    uint32_t a;
    asm("{ .reg .u64 t; cvta.to.shared.u64 t, %1; cvt.u32.u64 %0, t; }" : "=r"(a) : "l"(p));
    return a;
}

__device__ __forceinline__ void cp_async16(uint32_t dst, const void* src) {
    asm volatile("cp.async.cg.shared.global [%0], [%1], 16;\n" :: "r"(dst), "l"(src));
}
#define CP_COMMIT() asm volatile("cp.async.commit_group;\n" ::: "memory")
#define CP_WAIT2()  asm volatile("cp.async.wait_group 2;\n" ::: "memory")
#define CP_WAIT1()  asm volatile("cp.async.wait_group 1;\n" ::: "memory")
#define CP_WAIT0()  asm volatile("cp.async.wait_group 0;\n" ::: "memory")

__device__ __forceinline__ void ldsm_x4(uint32_t* r, uint32_t addr) {
    asm volatile("ldmatrix.sync.aligned.m8n8.x4.shared.b16 {%0,%1,%2,%3}, [%4];"
                 : "=r"(r[0]), "=r"(r[1]), "=r"(r[2]), "=r"(r[3]) : "r"(addr));
}

__device__ __forceinline__ void ldsm_x4_t(uint32_t* r, uint32_t addr) {
    asm volatile("ldmatrix.sync.aligned.m8n8.x4.trans.shared.b16 {%0,%1,%2,%3}, [%4];"
                 : "=r"(r[0]), "=r"(r[1]), "=r"(r[2]), "=r"(r[3]) : "r"(addr));
}

// fp16 HMMA, fp32 accumulate
__device__ __forceinline__ void mma_f16(float* d, const uint32_t* a, const uint32_t* b) {
    asm volatile("mma.sync.aligned.m16n8k16.row.col.f32.f16.f16.f32 "
                 "{%0,%1,%2,%3}, {%4,%5,%6,%7}, {%8,%9}, {%0,%1,%2,%3};"
                 : "+f"(d[0]), "+f"(d[1]), "+f"(d[2]), "+f"(d[3])
                 : "r"(a[0]), "r"(a[1]), "r"(a[2]), "r"(a[3]), "r"(b[0]), "r"(b[1]));
}

// pack two fp32 into f16x2 (lo -> low half)
__device__ __forceinline__ uint32_t pack_f16(float lo, float hi) {
    uint32_t d;
    asm("cvt.rn.f16x2.f32 %0, %1, %2;" : "=r"(d) : "f"(hi), "f"(lo));
    return d;
}

// ---------------------------------------------------------------------------
// Pure fp16 HMMA GEMM (1-pass): C = A[M,K] @ W[N,K]^T   (R16 verbatim)
// OUT==0: write fp32 C (+bias).  OUT==2: fp16.
// Block 128x128, BK=64, 256 threads, 2 CTAs/SM, 3-stage cp.async pipeline,
// XOR-swizzled 128B-row smem. Prefetch after compute.
// ---------------------------------------------------------------------------
#define GK     1024
#define BK     64
#define NITER  (GK / BK)               // 16
#define TILEB  (128 * 128)             // 16 KB: [128 rows][64 f16 = 128B]
#define STAGEB (2 * TILEB)             // 32 KB (A, W)
#define NSTAGE 3
#define GEMM_SMEM (NSTAGE * STAGEB)    // 96 KB

template<int OUT>
__global__ __launch_bounds__(256, 2) void gemm_mma(
    const __half* __restrict__ Ahi,
    const __half* __restrict__ Whi,
    const float* __restrict__ bias, float* __restrict__ C,
    __half* __restrict__ Chi, int N)
{
    extern __shared__ char sm[];
    const uint32_t sbase = smem_u32(sm);
    const int tid  = threadIdx.x;
    const int lane = tid & 31;
    const int warp = tid >> 5;
    const int wm = warp & 1;
    const int wn = warp >> 1;
    const int m0 = blockIdx.y * 128;
    const int n0 = blockIdx.x * 128;

    float acc[4][4][4];
    #pragma unroll
    for (int i = 0; i < 4; i++)
        #pragma unroll
        for (int j = 0; j < 4; j++)
            #pragma unroll
            for (int q = 0; q < 4; q++) acc[i][j][q] = 0.f;

    auto soff = [&](int s, int t) -> uint32_t { return sbase + s * STAGEB + t * TILEB; };

    auto load_stage = [&](int s, int k0) {
        const __half* gsrc[2] = {Ahi + (size_t)m0 * GK + k0,
                                 Whi + (size_t)n0 * GK + k0};
        #pragma unroll
        for (int t = 0; t < 2; t++) {
            const char* gp = (const char*)gsrc[t];
            #pragma unroll
            for (int j = 0; j < 4; j++) {
                int id = tid + j * 256;           // 0..1023
                int r = id >> 3, c = id & 7;
                uint32_t sw = r * 128 + ((c ^ (r & 7)) << 4);
                cp_async16(soff(s, t) + sw, gp + (size_t)r * (GK * 2) + c * 16);
            }
        }
        CP_COMMIT();
    };

    load_stage(0, 0);
    load_stage(1, BK);

    const int sub = lane >> 3, rin = lane & 7;
    const int a_row_off = (sub & 1) * 8 + rin;
    const int a_chunk   = sub >> 1;
    const int b_row_off = (sub >> 1) * 8 + rin;
    const int b_chunk   = sub & 1;

    for (int it = 0; it < NITER; it++) {
        const int s = it % NSTAGE;
        if (it == NITER - 1) { CP_WAIT0(); } else { CP_WAIT1(); }
        __syncthreads();

        const uint32_t aH = soff(s, 0), wH = soff(s, 1);

        #pragma unroll
        for (int ks = 0; ks < 4; ks++) {          // 4 k16 steps per BK=64
            uint32_t Ah[4][4], Bh[4][2];

            #pragma unroll
            for (int mi = 0; mi < 4; mi++) {
                int row = wm * 64 + mi * 16 + a_row_off;
                int ch = ks * 2 + a_chunk;
                uint32_t off = row * 128 + ((ch ^ (row & 7)) << 4);
                ldsm_x4(Ah[mi], aH + off);
            }
            #pragma unroll
            for (int p = 0; p < 2; p++) {
                int row = wn * 32 + p * 16 + b_row_off;
                int ch = ks * 2 + b_chunk;
                uint32_t off = row * 128 + ((ch ^ (row & 7)) << 4);
                uint32_t t0[4];
                ldsm_x4(t0, wH + off);
                Bh[p*2  ][0] = t0[0]; Bh[p*2  ][1] = t0[1];
                Bh[p*2+1][0] = t0[2]; Bh[p*2+1][1] = t0[3];
            }

            #pragma unroll
            for (int mi = 0; mi < 4; mi++)
                #pragma unroll
                for (int ni = 0; ni < 4; ni++)
                    mma_f16(acc[mi][ni], Ah[mi], Bh[ni]);
        }
        if (it + 2 < NITER) load_stage((it + 2) % NSTAGE, (it + 2) * BK);
    }

    const int g = lane >> 2, c2 = (lane & 3) * 2;
    #pragma unroll
    for (int mi = 0; mi < 4; mi++) {
        int row = m0 + wm * 64 + mi * 16 + g;
        #pragma unroll
        for (int ni = 0; ni < 4; ni++) {
            int col = n0 + wn * 32 + ni * 8 + c2;
            if (OUT == 0) {
                float b0 = 0.f, b1 = 0.f;
                if (bias) { b0 = bias[col]; b1 = bias[col + 1]; }
                float2 v0 = make_float2(acc[mi][ni][0] + b0, acc[mi][ni][1] + b1);
                float2 v1 = make_float2(acc[mi][ni][2] + b0, acc[mi][ni][3] + b1);
                *(float2*)&C[(size_t)row * N + col] = v0;
                *(float2*)&C[(size_t)(row + 8) * N + col] = v1;
            } else {
                *(uint32_t*)&Chi[(size_t)row * N + col] =
                    pack_f16(acc[mi][ni][0], acc[mi][ni][1]);
                *(uint32_t*)&Chi[(size_t)(row + 8) * N + col] =
                    pack_f16(acc[mi][ni][2], acc[mi][ni][3]);
            }
        }
    }
}

// ---------------------------------------------------------------------------
// Fused preprocessing: one launch does all three casts concurrently.
//   blocks [0, XB):        x fp32 -> fp16            (8192 blocks)
//   blocks [XB, XB+W1B):   w_qkv [K][N] -> w1^T fp16 (3072 blocks, 32x32 tiles)
//   blocks [XB+W1B, ...):  w_out [K][N] -> w2^T fp16 (1024 blocks)
// ---------------------------------------------------------------------------
#define XB   (TOKENS * DIM / 4 / 256)        // 8192
#define W1B  ((QKVDIM / 32) * (DIM / 32))    // 3072
#define W2B  ((DIM / 32) * (DIM / 32))       // 1024
#define CAST_BLOCKS (XB + W1B + W2B)         // 12288

__global__ __launch_bounds__(256) void cast_all(
    const float* __restrict__ x,  __half* __restrict__ xhi,
    const float* __restrict__ w1, __half* __restrict__ w1t,
    const float* __restrict__ w2, __half* __restrict__ w2t)
{
    __shared__ float t[32][33];
    const int bid = blockIdx.x;

    if (bid < XB) {
        int i = bid * 256 + threadIdx.x;
        float4 v = ((const float4*)x)[i];
        ((uint2*)xhi)[i] = make_uint2(pack_f16(v.x, v.y), pack_f16(v.z, v.w));
        return;
    }

    const float* w;
    __half* wt;
    int b, N;
    if (bid < XB + W1B) { b = bid - XB;        w = w1; wt = w1t; N = QKVDIM; }
    else                { b = bid - XB - W1B;  w = w2; wt = w2t; N = DIM;    }

    const int nt = N / 32;
    const int n0 = (b % nt) * 32, k0 = (b / nt) * 32;
    const int tx = threadIdx.x & 31, ty = threadIdx.x >> 5;
    #pragma unroll
    for (int j = ty; j < 32; j += 8)
        t[j][tx] = w[(size_t)(k0 + j) * N + n0 + tx];
    __syncthreads();
    #pragma unroll
    for (int j = ty; j < 32; j += 8)
        wt[(size_t)(n0 + j) * GK + k0 + tx] = __float2half_rn(t[tx][j]);
}

// ---------------------------------------------------------------------------
// HMMA flash attention, pure fp16 (R16 verbatim).
// S = Qh Kh^T; O += Ph Vh. 3-stage KV ring, exp2-domain softmax.
// smem: Q 16KB + 3 x 16KB = 64 KB; 2 CTAs/SM.
// ---------------------------------------------------------------------------
#define AT_Q    0
#define AT_ST   16384
#define AT_STB  16384
#define AT_KH   0
#define AT_VH   8192
#define AT_NST  3
#define AT_SMEM (AT_ST + AT_NST * AT_STB)   // 65536

__global__ __launch_bounds__(256, 2) void attn_mma(
    const __half* __restrict__ qh, __half* __restrict__ ohi)
{
    extern __shared__ char sm[];
    const uint32_t sb = smem_u32(sm);
    const int tid  = threadIdx.x;
    const int lane = tid & 31;
    const int warp = tid >> 5;
    const int sub = lane >> 3, rin = lane & 7;
    const int g = lane >> 2, t = lane & 3;

    const int qt = blockIdx.x, head = blockIdx.y, batch = blockIdx.z;
    const size_t tok0 = (size_t)batch * SEQ;
    const size_t qbase = (tok0 + qt * 128) * QKVDIM + head * HDIM;

    #pragma unroll
    for (int j = 0; j < 4; j++) {
        int id = tid + j * 256;
        int r = id >> 3, c = id & 7;
        uint32_t sw = r * 128 + ((c ^ (r & 7)) << 4);
        cp_async16(sb + AT_Q + sw, (const char*)(qh + qbase) + (size_t)r * QKVDIM * 2 + c * 16);
    }
    CP_COMMIT();

    auto load_kv = [&](int s, int jt) {
        size_t kb = (tok0 + jt * 64) * QKVDIM + DIM + head * HDIM;
        size_t vb = kb + DIM;
        uint32_t st = sb + AT_ST + s * AT_STB;
        #pragma unroll
        for (int j = 0; j < 2; j++) {
            int id = tid + j * 256;
            int r = id >> 3, c = id & 7;
            uint32_t sw = r * 128 + ((c ^ (r & 7)) << 4);
            size_t go = (size_t)r * QKVDIM * 2 + c * 16;
            cp_async16(st + AT_KH + sw, (const char*)(qh + kb) + go);
            cp_async16(st + AT_VH + sw, (const char*)(qh + vb) + go);
        }
        CP_COMMIT();
    };

    load_kv(0, 0);
    load_kv(1, 1);

    CP_WAIT2();
    __syncthreads();
    uint32_t Qh[4][4];
    {
        int row = warp * 16 + (sub & 1) * 8 + rin;
        #pragma unroll
        for (int s4 = 0; s4 < 4; s4++) {
            int ch = 2 * s4 + (sub >> 1);
            uint32_t off = row * 128 + ((ch ^ (row & 7)) << 4);
            ldsm_x4(Qh[s4], sb + AT_Q + off);
        }
    }

    float m0 = -1e30f, m1 = -1e30f, l0 = 0.f, l1 = 0.f;
    float O[8][4];
    #pragma unroll
    for (int b = 0; b < 8; b++)
        #pragma unroll
        for (int q = 0; q < 4; q++) O[b][q] = 0.f;

    const int NT = SEQ / 64;          // 16 KV tiles
    for (int jt = 0; jt < NT; jt++) {
        const int s = jt % AT_NST;
        if (jt == NT - 1) { CP_WAIT0(); } else { CP_WAIT1(); }
        __syncthreads();              // only barrier per tile (3-stage ring)
        const uint32_t stb = sb + AT_ST + s * AT_STB;

        float S[8][4];
        #pragma unroll
        for (int b = 0; b < 8; b++)
            #pragma unroll
            for (int q = 0; q < 4; q++) S[b][q] = 0.f;

        #pragma unroll
        for (int s4 = 0; s4 < 4; s4++) {
            int bch = 2 * s4 + (sub & 1);
            #pragma unroll
            for (int jp = 0; jp < 4; jp++) {
                int row = jp * 16 + (sub >> 1) * 8 + rin;
                uint32_t off = row * 128 + ((bch ^ (row & 7)) << 4);
                uint32_t kh[4];
                ldsm_x4(kh, stb + AT_KH + off);
                mma_f16(S[2*jp],   Qh[s4], kh);
                mma_f16(S[2*jp+1], Qh[s4], kh + 2);
            }
        }

        // exp2-domain online softmax
        float mx0 = -1e30f, mx1 = -1e30f;
        #pragma unroll
        for (int b = 0; b < 8; b++) {
            #pragma unroll
            for (int q = 0; q < 4; q++) S[b][q] *= SCALE2;
            mx0 = fmaxf(mx0, fmaxf(S[b][0], S[b][1]));
            mx1 = fmaxf(mx1, fmaxf(S[b][2], S[b][3]));
        }
        #pragma unroll
        for (int off = 1; off < 4; off <<= 1) {
            mx0 = fmaxf(mx0, __shfl_xor_sync(0xffffffffu, mx0, off));
            mx1 = fmaxf(mx1, __shfl_xor_sync(0xffffffffu, mx1, off));
        }
        float mn0 = fmaxf(m0, mx0), mn1 = fmaxf(m1, mx1);
        float al0 = exp2f(m0 - mn0), al1 = exp2f(m1 - mn1);
        m0 = mn0; m1 = mn1;

        float rs0 = 0.f, rs1 = 0.f;
        #pragma unroll
        for (int b = 0; b < 8; b++) {
            S[b][0] = exp2f(S[b][0] - mn0); rs0 += S[b][0];
            S[b][1] = exp2f(S[b][1] - mn0); rs0 += S[b][1];
            S[b][2] = exp2f(S[b][2] - mn1); rs1 += S[b][2];
            S[b][3] = exp2f(S[b][3] - mn1); rs1 += S[b][3];
        }
        #pragma unroll
        for (int off = 1; off < 4; off <<= 1) {
            rs0 += __shfl_xor_sync(0xffffffffu, rs0, off);
            rs1 += __shfl_xor_sync(0xffffffffu, rs1, off);
        }
        l0 = l0 * al0 + rs0;
        l1 = l1 * al1 + rs1;
        #pragma unroll
        for (int b = 0; b < 8; b++) {
            O[b][0] *= al0; O[b][1] *= al0;
            O[b][2] *= al1; O[b][3] *= al1;
        }

        // O += Ph Vh (1-pass)
        #pragma unroll
        for (int a = 0; a < 4; a++) {
            uint32_t Ph[4];
            Ph[0] = pack_f16(S[2*a][0],   S[2*a][1]);
            Ph[1] = pack_f16(S[2*a][2],   S[2*a][3]);
            Ph[2] = pack_f16(S[2*a+1][0], S[2*a+1][1]);
            Ph[3] = pack_f16(S[2*a+1][2], S[2*a+1][3]);

            int vrow = a * 16 + (sub & 1) * 8 + rin;
            #pragma unroll
            for (int bp = 0; bp < 4; bp++) {
                int ch = 2 * bp + (sub >> 1);
                uint32_t off = vrow * 128 + ((ch ^ (vrow & 7)) << 4);
                uint32_t vh[4];
                ldsm_x4_t(vh, stb + AT_VH + off);
                mma_f16(O[2*bp],   Ph, vh);
                mma_f16(O[2*bp+1], Ph, vh + 2);
            }
        }
        if (jt + 2 < NT) load_kv((jt + 2) % AT_NST, jt + 2);
    }

    float inv0 = 1.f / l0, inv1 = 1.f / l1;
    size_t t0 = tok0 + qt * 128 + warp * 16 + g;
    size_t t1 = t0 + 8;
    #pragma unroll
    for (int b = 0; b < 8; b++) {
        int col = head * HDIM + b * 8 + 2 * t;
        *(uint32_t*)&ohi[t0 * DIM + col] = pack_f16(O[b][0] * inv0, O[b][1] * inv0);
        *(uint32_t*)&ohi[t1 * DIM + col] = pack_f16(O[b][2] * inv1, O[b][3] * inv1);
    }
}

// ----------------------------------------------------------------------------
// Launch
// ----------------------------------------------------------------------------
extern "C" void kernel_launch(void* const* d_in, const int* in_sizes, int n_in,
                              void* d_out, int out_size)
{
    const float* x     = (const float*)d_in[0];
    const float* w_qkv = (const float*)d_in[1];
    const float* w_out = (const float*)d_in[2];
    const float* b_out = (const float*)d_in[3];
    float* out = (float*)d_out;

    void *p_xhi, *p_w1hi, *p_w2hi, *p_qh, *p_ahi;
    cudaGetSymbolAddress(&p_xhi, g_xhi);
    cudaGetSymbolAddress(&p_w1hi, g_w1hi);
    cudaGetSymbolAddress(&p_w2hi, g_w2hi);
    cudaGetSymbolAddress(&p_qh, g_qkvhi);
    cudaGetSymbolAddress(&p_ahi, g_ahi);

    cudaFuncSetAttribute(gemm_mma<0>, cudaFuncAttributeMaxDynamicSharedMemorySize, GEMM_SMEM);
    cudaFuncSetAttribute(gemm_mma<2>, cudaFuncAttributeMaxDynamicSharedMemorySize, GEMM_SMEM);
    cudaFuncSetAttribute(attn_mma,    cudaFuncAttributeMaxDynamicSharedMemorySize, AT_SMEM);

    // 0) all three casts in ONE launch (x, w_qkv^T, w_out^T concurrently)
    cast_all<<<CAST_BLOCKS, 256>>>(
        x, (__half*)p_xhi,
        w_qkv, (__half*)p_w1hi,
        w_out, (__half*)p_w2hi);

    // 1) qkv = x @ w_qkv -> fp16 (1-pass, BK=64)            [8192, 3072]
    gemm_mma<2><<<dim3(QKVDIM / 128, TOKENS / 128), 256, GEMM_SMEM>>>(
        (const __half*)p_xhi, (const __half*)p_w1hi,
        nullptr, nullptr, (__half*)p_qh, QKVDIM);

    // 2) attention -> fp16 (3-stage KV ring)                 [8192, 1024]
    attn_mma<<<dim3(SEQ / 128, HEADS, BATCH), 256, AT_SMEM>>>(
        (const __half*)p_qh, (__half*)p_ahi);

    // 3) out = attn @ w_out + b (1-pass, BK=64)              [8192, 1024]
    gemm_mma<0><<<dim3(DIM / 128, TOKENS / 128), 256, GEMM_SMEM>>>(
        (const __half*)p_ahi, (const __half*)p_w2hi,
        b_out, out, nullptr, DIM);
}